// round 6
// baseline (speedup 1.0000x reference)
#include <cuda_runtime.h>
#include <math.h>
#include <stdint.h>

// ---------------- problem constants ----------------
#define L_TOK   4096
#define DMODEL  3584
#define NH      112
#define HD      64
#define DS      64
#define CHUNKSZ 256
#define NCHUNK  16
#define NG      2
#define HPG     (NH / NG)          // 56
#define INNER   (NH * HD)          // 7168
#define IN2     (2 * INNER)        // 14336

// ---------------- scratch (device globals; no cudaMalloc allowed) ----------
__device__ float g_xz[(size_t)L_TOK * IN2];            // [x | z]
__device__ float g_yg[(size_t)L_TOK * INNER];          // gated y (tf32-rounded)
__device__ float g_states[(size_t)NCHUNK * NH * HD * DS];   // [k][h][p][n]
__device__ float g_prev[(size_t)NCHUNK * NH * DS * HD];     // [k][h][n][p]
__device__ float g_hid[(size_t)L_TOK * DMODEL];        // tf32-rounded hidden
__device__ float g_w1[(size_t)IN2 * DMODEL];           // tf32-rounded W_in
__device__ float g_w2[(size_t)DMODEL * INNER];         // tf32-rounded W_out
__device__ float g_dt[NH];
__device__ float g_a[NH];

// ---------------- helpers ---------------------------------------------------
__device__ __forceinline__ uint32_t s2u(const void* p) {
    uint32_t a;
    asm("{ .reg .u64 t; cvta.to.shared.u64 t, %1; cvt.u32.u64 %0, t; }"
        : "=r"(a) : "l"(p));
    return a;
}
__device__ __forceinline__ void cpasync16(uint32_t saddr, const void* g) {
    asm volatile("cp.async.cg.shared.global [%0], [%1], 16;" :: "r"(saddr), "l"(g));
}
__device__ __forceinline__ float rtf32(float x) {
    uint32_t r;
    asm("cvt.rna.tf32.f32 %0, %1;" : "=r"(r) : "f"(x));
    return __uint_as_float(r);
}
__device__ __forceinline__ void ffma2(float2 &d, const float2 &a, const float2 &b) {
    unsigned long long ud, ua, ub;
    __builtin_memcpy(&ud, &d, 8);
    __builtin_memcpy(&ua, &a, 8);
    __builtin_memcpy(&ub, &b, 8);
    asm("fma.rn.f32x2 %0, %1, %2, %0;" : "+l"(ud) : "l"(ua), "l"(ub));
    __builtin_memcpy(&d, &ud, 8);
}
__device__ __forceinline__ void ldsm4(uint32_t* r, uint32_t addr) {
    asm volatile("ldmatrix.sync.aligned.m8n8.x4.shared.b16 {%0,%1,%2,%3}, [%4];"
                 : "=r"(r[0]), "=r"(r[1]), "=r"(r[2]), "=r"(r[3]) : "r"(addr));
}
__device__ __forceinline__ void mma16n8k8(float* d, const uint32_t* a,
                                          uint32_t b0, uint32_t b1) {
    asm volatile(
        "mma.sync.aligned.m16n8k8.row.col.f32.tf32.tf32.f32 "
        "{%0,%1,%2,%3}, {%4,%5,%6,%7}, {%8,%9}, {%0,%1,%2,%3};"
        : "+f"(d[0]), "+f"(d[1]), "+f"(d[2]), "+f"(d[3])
        : "r"(a[0]), "r"(a[1]), "r"(a[2]), "r"(a[3]), "r"(b0), "r"(b1));
}

// ---------------- per-head parameters --------------------------------------
__global__ void hparams_kernel(const float* __restrict__ A_log,
                               const float* __restrict__ dt_bias) {
    int h = threadIdx.x;
    if (h < NH) {
        float xv = 0.1f + dt_bias[h];
        float sp = (xv > 20.f) ? xv : log1pf(expf(xv));
        g_dt[h] = sp;
        g_a[h]  = -expf(A_log[h]) * sp;
    }
}

// ---------------- round-to-nearest tf32 preprocessing ----------------------
__global__ void round_tf32_kernel(const float* __restrict__ in, float* __restrict__ out, int n4) {
    int i = blockIdx.x * blockDim.x + threadIdx.x;
    int stride = gridDim.x * blockDim.x;
    for (; i < n4; i += stride) {
        float4 v = ((const float4*)in)[i];
        v.x = rtf32(v.x); v.y = rtf32(v.y); v.z = rtf32(v.z); v.w = rtf32(v.w);
        ((float4*)out)[i] = v;
    }
}

// ---------------- mma.sync TF32 GEMM: C[M,N] = A[M,K]*B[N,K]^T -------------
// Block 128(M) x 128(N) x 32(K); 256 threads = 8 warps as 2(m) x 4(n);
// warp tile 64x32. ldmatrix fragments. 3-stage cp.async. 2 CTAs/SM.
#define KT       32
#define ALD      36
#define A_FLT    (128 * ALD)                 // 4608 floats
#define B_FLT    (128 * ALD)                 // 4608 floats
#define STG_FLT  (A_FLT + B_FLT)             // 9216 floats
#define STGB     (STG_FLT * 4)               // 36864 B
#define NSTG     3
#define GM_SMEM  (NSTG * STGB)               // 110592 B

__global__ __launch_bounds__(256, 2)
void gemm_mma(const float* __restrict__ A, const float* __restrict__ B,
              float* __restrict__ C, int M, int N, int K, int tiles_m) {
    extern __shared__ __align__(16) float sm[];
    uint32_t sbase = s2u(sm);

    int tid = threadIdx.x, lane = tid & 31, wid = tid >> 5;
    int wm = (wid & 1) * 64;
    int wn = (wid >> 1) * 32;
    int bid = blockIdx.x;
    int m0 = (bid % tiles_m) * 128;
    int n0 = (bid / tiles_m) * 128;

    // cp.async: base pointer + per-iter stride (saves registers)
    int r0l = tid >> 3, c4l = (tid & 7) * 4;
    const float* gA0 = A + (size_t)(m0 + r0l) * K + c4l;
    const float* gB0 = B + (size_t)(n0 + r0l) * K + c4l;
    uint32_t oA0 = (uint32_t)(r0l * ALD + c4l) * 4;
    uint32_t oB0 = (uint32_t)(A_FLT + r0l * ALD + c4l) * 4;
    const size_t gstep = (size_t)32 * K;        // 32 rows per iter
    const uint32_t ostep = 32 * ALD * 4;

    // ldmatrix per-lane addresses
    int lr = lane & 7;
    int a_row = lr + ((lane >> 3) & 1) * 8;
    int a_col = ((lane >> 4) & 1) * 4;
    uint32_t aoff0 = sbase + (uint32_t)(((wm + a_row) * ALD + a_col) * 4);
    int b_row = lr + ((lane >> 4) & 1) * 8;
    int b_col = ((lane >> 3) & 1) * 4;
    uint32_t boff0 = sbase + (uint32_t)((A_FLT + (wn + b_row) * ALD + b_col) * 4);

    const int NKC = K / KT;

    #pragma unroll
    for (int s = 0; s < NSTG - 1; s++) {
        uint32_t sb = sbase + s * STGB;
        #pragma unroll
        for (int it = 0; it < 4; it++) {
            cpasync16(sb + oA0 + it * ostep, gA0 + it * gstep + s * KT);
            cpasync16(sb + oB0 + it * ostep, gB0 + it * gstep + s * KT);
        }
        asm volatile("cp.async.commit_group;");
    }

    float acc[4][4][4];
    #pragma unroll
    for (int t = 0; t < 4; t++)
        #pragma unroll
        for (int u = 0; u < 4; u++)
            #pragma unroll
            for (int v = 0; v < 4; v++) acc[t][u][v] = 0.f;

    for (int kb = 0; kb < NKC; kb++) {
        int st = kb % NSTG;
        asm volatile("cp.async.wait_group %0;" :: "n"(NSTG - 2));
        __syncthreads();

        {
            int fc = kb + NSTG - 1;
            if (fc < NKC) {
                uint32_t sb = sbase + (fc % NSTG) * STGB;
                #pragma unroll
                for (int it = 0; it < 4; it++) {
                    cpasync16(sb + oA0 + it * ostep, gA0 + it * gstep + fc * KT);
                    cpasync16(sb + oB0 + it * ostep, gB0 + it * gstep + fc * KT);
                }
            }
            asm volatile("cp.async.commit_group;");
        }

        uint32_t stb = st * STGB;
        #pragma unroll
        for (int ks = 0; ks < 4; ks++) {
            uint32_t kadd = stb + ks * 32;
            uint32_t af[4][4];
            #pragma unroll
            for (int t = 0; t < 4; t++) ldsm4(af[t], aoff0 + t * (16 * ALD * 4) + kadd);
            uint32_t bf[2][4];
            #pragma unroll
            for (int v = 0; v < 2; v++) ldsm4(bf[v], boff0 + v * (16 * ALD * 4) + kadd);
            #pragma unroll
            for (int u = 0; u < 4; u++) {
                uint32_t b0 = bf[u >> 1][(u & 1) * 2 + 0];
                uint32_t b1 = bf[u >> 1][(u & 1) * 2 + 1];
                #pragma unroll
                for (int t = 0; t < 4; t++) mma16n8k8(acc[t][u], af[t], b0, b1);
            }
        }
    }

    int g4 = lane >> 2, c4i = lane & 3;
    #pragma unroll
    for (int t = 0; t < 4; t++) {
        int r0 = m0 + wm + t * 16 + g4;
        #pragma unroll
        for (int u = 0; u < 4; u++) {
            int col = n0 + wn + u * 8 + c4i * 2;
            *(float2*)&C[(size_t)r0 * N + col] = make_float2(acc[t][u][0], acc[t][u][1]);
            *(float2*)&C[(size_t)(r0 + 8) * N + col] = make_float2(acc[t][u][2], acc[t][u][3]);
        }
    }
}

// ---------------- per-chunk end states: S[k,h,p,n] --------------------------
__global__ void states_kernel(const float* __restrict__ Bin) {
    int k = blockIdx.x, h = blockIdx.y;
    int tid = threadIdx.x;
    int p = tid & 63, quad = tid >> 6;
    float a = g_a[h], dtv = g_dt[h];
    int g = h / HPG;
    __shared__ float sx[8 * 64], sbuf[8 * 64];
    float acc[16];
    #pragma unroll
    for (int m = 0; m < 16; m++) acc[m] = 0.f;
    int lb = k * CHUNKSZ;
    for (int jb = 0; jb < CHUNKSZ; jb += 8) {
        __syncthreads();
        #pragma unroll
        for (int it = 0; it < 2; it++) {
            int e = tid + it * 256;
            int jj = e >> 6, pp = e & 63;
            int l = lb + jb + jj;
            sx[e] = g_xz[(size_t)l * IN2 + h * HD + pp];
            sbuf[e] = Bin[((size_t)l * NG + g) * DS + pp];
        }
        __syncthreads();
        #pragma unroll
        for (int jj = 0; jj < 8; jj++) {
            int j = jb + jj;
            float dec = expf(a * (float)(CHUNKSZ - 1 - j)) * dtv;
            float v = sx[jj * 64 + p] * dec;
            #pragma unroll
            for (int m = 0; m < 16; m++)
                acc[m] += v * sbuf[jj * 64 + quad + 4 * m];
        }
    }
    size_t base = ((size_t)(k * NH + h)) << 12;
    #pragma unroll
    for (int m = 0; m < 16; m++)
        g_states[base + p * 64 + quad + 4 * m] = acc[m];
}

// ---------------- inter-chunk scan -----------------------------------------
__global__ void scan_kernel() {
    int h = blockIdx.x;
    float cd = expf(g_a[h] * (float)CHUNKSZ);
    for (int e = threadIdx.x; e < HD * DS; e += 256) {
        int p = e >> 6, n = e & 63;
        float carry = 0.f;
        #pragma unroll
        for (int k = 0; k < NCHUNK; k++) {
            size_t base = ((size_t)(k * NH + h)) << 12;
            g_prev[base + n * 64 + p] = carry;
            carry = carry * cd + g_states[base + e];
        }
    }
}

// ---------------- intra-chunk + off-diagonal + gate (f32x2 packed) ----------
// Warp->row-group remap {0,2,4,6,7,5,3,1} balances the triangular work across
// SMSPs (pairs heavy+light groups on each scheduler).
#define CLD 65
#define SY_FLOATS (256*64 + 256*64 + 64*64 + 256*CLD + 288)
__global__ __launch_bounds__(256, 1)
void yblock_kernel(const float* __restrict__ Bin, const float* __restrict__ Cin,
                   const float* __restrict__ Dv) {
    extern __shared__ float sm[];
    float* sX   = sm;
    float* sB   = sX + 256 * 64;
    float* sP   = sB + 256 * 64;
    float* sC   = sP + 64 * 64;
    float* sDec = sC + 256 * CLD;

    int k = blockIdx.x, h = blockIdx.y;
    int tid = threadIdx.x;
    int lane = tid & 31, wid = tid >> 5;
    float a = g_a[h], dtv = g_dt[h], Dh = Dv[h];
    int g = h / HPG;
    int lb = k * CHUNKSZ;

    float4* sX4 = (float4*)sX;
    float4* sB4 = (float4*)sB;
    float4* sP4 = (float4*)sP;
    #pragma unroll
    for (int it = 0; it < 16; it++) {
        int q = tid + it * 256;
        int j = q >> 4, p4 = q & 15;
        sX4[q] = *(const float4*)&g_xz[(size_t)(lb + j) * IN2 + h * HD + p4 * 4];
        sB4[q] = *(const float4*)&Bin[((size_t)(lb + j) * NG + g) * DS + p4 * 4];
    }
    {
        size_t pbase = ((size_t)(k * NH + h)) << 12;
        #pragma unroll
        for (int it = 0; it < 4; it++) {
            int q = tid + it * 256;
            sP4[q] = *(const float4*)&g_prev[pbase + (size_t)q * 4];
        }
    }
    for (int d = tid; d < CHUNKSZ + 1; d += 256) sDec[d] = expf(a * (float)d);

    // balanced row assignment: remap[w] = w<4 ? 2w : 15-2w
    int rg = (wid < 4) ? (2 * wid) : (15 - 2 * wid);
    int i = rg * 32 + lane;

    float2 cre2[32];
    {
        const float4* Crow = (const float4*)&Cin[((size_t)(lb + i) * NG + g) * DS];
        #pragma unroll
        for (int n4 = 0; n4 < 16; n4++) {
            float4 v = Crow[n4];
            cre2[2 * n4 + 0] = make_float2(v.x, v.y);
            cre2[2 * n4 + 1] = make_float2(v.z, v.w);
            sC[i * CLD + 4 * n4 + 0] = v.x;
            sC[i * CLD + 4 * n4 + 1] = v.y;
            sC[i * CLD + 4 * n4 + 2] = v.z;
            sC[i * CLD + 4 * n4 + 3] = v.w;
        }
    }
    __syncthreads();

    float2 acc2[32];
    #pragma unroll
    for (int p = 0; p < 32; p++) acc2[p] = make_float2(0.f, 0.f);

    for (int j = 0; j <= i; j++) {
        const float4* bj = (const float4*)&sB[j * 64];
        float2 s2 = make_float2(0.f, 0.f);
        #pragma unroll
        for (int m4 = 0; m4 < 16; m4++) {
            float4 bv = bj[m4];
            ffma2(s2, cre2[2 * m4 + 0], make_float2(bv.x, bv.y));
            ffma2(s2, cre2[2 * m4 + 1], make_float2(bv.z, bv.w));
        }
        float w = (s2.x + s2.y) * sDec[i - j] * dtv;
        float2 w2 = make_float2(w, w);
        const float4* xj = (const float4*)&sX[j * 64];
        #pragma unroll
        for (int p4 = 0; p4 < 16; p4++) {
            float4 xv = xj[p4];
            ffma2(acc2[2 * p4 + 0], w2, make_float2(xv.x, xv.y));
            ffma2(acc2[2 * p4 + 1], w2, make_float2(xv.z, xv.w));
        }
    }
    {
        float coef = sDec[i + 1];
        for (int n = 0; n < 64; n++) {
            float w = sC[i * CLD + n] * coef;
            float2 w2 = make_float2(w, w);
            const float4* pn = (const float4*)&sP[n * 64];
            #pragma unroll
            for (int p4 = 0; p4 < 16; p4++) {
                float4 pv = pn[p4];
                ffma2(acc2[2 * p4 + 0], w2, make_float2(pv.x, pv.y));
                ffma2(acc2[2 * p4 + 1], w2, make_float2(pv.z, pv.w));
            }
        }
    }
    {
        int l = lb + i;
        const float* zrow = &g_xz[(size_t)l * IN2 + INNER + h * HD];
        const float* xrow = &sX[i * 64];
        float* outp = &g_yg[(size_t)l * INNER + h * HD];
        #pragma unroll
        for (int p4 = 0; p4 < 16; p4++) {
            float4 zv = *(const float4*)&zrow[p4 * 4];
            float4 xv = *(const float4*)&xrow[p4 * 4];
            float4 o;
            o.x = rtf32((acc2[2 * p4 + 0].x + xv.x * Dh) / (1.f + expf(-zv.x)));
            o.y = rtf32((acc2[2 * p4 + 0].y + xv.y * Dh) / (1.f + expf(-zv.y)));
            o.z = rtf32((acc2[2 * p4 + 1].x + xv.z * Dh) / (1.f + expf(-zv.z)));
            o.w = rtf32((acc2[2 * p4 + 1].y + xv.w * Dh) / (1.f + expf(-zv.w)));
            *(float4*)&outp[p4 * 4] = o;
        }
    }
}

// ---------------- launcher --------------------------------------------------
extern "C" void kernel_launch(void* const* d_in, const int* in_sizes, int n_in,
                              void* d_out, int out_size) {
    (void)in_sizes; (void)n_in; (void)out_size;
    const float* hidden = (const float*)d_in[0];
    const float* W_in   = (const float*)d_in[1];
    const float* W_out  = (const float*)d_in[2];
    const float* A_log  = (const float*)d_in[3];
    const float* Dv     = (const float*)d_in[4];
    const float* dtb    = (const float*)d_in[5];
    const float* Bin    = (const float*)d_in[6];
    const float* Cin    = (const float*)d_in[7];
    float* out = (float*)d_out;

    float *xz_ptr, *yg_ptr, *hid_ptr, *w1_ptr, *w2_ptr;
    cudaGetSymbolAddress((void**)&xz_ptr, g_xz);
    cudaGetSymbolAddress((void**)&yg_ptr, g_yg);
    cudaGetSymbolAddress((void**)&hid_ptr, g_hid);
    cudaGetSymbolAddress((void**)&w1_ptr, g_w1);
    cudaGetSymbolAddress((void**)&w2_ptr, g_w2);

    cudaFuncSetAttribute(gemm_mma, cudaFuncAttributeMaxDynamicSharedMemorySize, GM_SMEM);

    // launch order chosen so gemm1 is the 4th launch (ncu captures it)
    hparams_kernel<<<1, 128>>>(A_log, dtb);                                   // 1
    round_tf32_kernel<<<1184, 256>>>(W_in,   w1_ptr,  (IN2 * DMODEL) / 4);    // 2
    round_tf32_kernel<<<1184, 256>>>(hidden, hid_ptr, (L_TOK * DMODEL) / 4);  // 3

    // GEMM1: xz[L, IN2] = hid[L, DMODEL] @ W_in[IN2, DMODEL]^T
    {
        int tiles_m = L_TOK / 128;      // 32
        int tiles_n = IN2 / 128;        // 112
        gemm_mma<<<tiles_m * tiles_n, 256, GM_SMEM>>>(hid_ptr, w1_ptr, xz_ptr,
                                                      L_TOK, IN2, DMODEL, tiles_m);  // 4
    }

    states_kernel<<<dim3(NCHUNK, NH), 256>>>(Bin);                            // 5
    scan_kernel<<<NH, 256>>>();                                               // 6

    {
        size_t smem = (size_t)SY_FLOATS * sizeof(float);
        cudaFuncSetAttribute(yblock_kernel,
                             cudaFuncAttributeMaxDynamicSharedMemorySize, (int)smem);
        yblock_kernel<<<dim3(NCHUNK, NH), 256, smem>>>(Bin, Cin, Dv);         // 7
    }

    round_tf32_kernel<<<1184, 256>>>(W_out, w2_ptr, (DMODEL * INNER) / 4);    // 8

    // GEMM2: out[L, DMODEL] = yg[L, INNER] @ W_out[DMODEL, INNER]^T
    {
        int tiles_m = L_TOK / 128;      // 32
        int tiles_n = DMODEL / 128;     // 28
        gemm_mma<<<tiles_m * tiles_n, 256, GM_SMEM>>>(yg_ptr, w2_ptr, out,
                                                      L_TOK, DMODEL, INNER, tiles_m); // 9
    }
}

// round 7
// speedup vs baseline: 1.0825x; 1.0825x over previous
#include <cuda_runtime.h>
#include <math.h>
#include <stdint.h>

// ---------------- problem constants ----------------
#define L_TOK   4096
#define DMODEL  3584
#define NH      112
#define HD      64
#define DS      64
#define CHUNKSZ 128
#define NCHUNK  32
#define NG      2
#define HPG     (NH / NG)          // 56
#define INNER   (NH * HD)          // 7168
#define IN2     (2 * INNER)        // 14336

// ---------------- scratch (device globals; no cudaMalloc allowed) ----------
__device__ float g_xz[(size_t)L_TOK * IN2];            // [x | z]
__device__ float g_yg[(size_t)L_TOK * INNER];          // gated y (tf32-rounded)
__device__ float g_states[(size_t)NCHUNK * NH * HD * DS];   // [k][h][p][n]
__device__ float g_prev[(size_t)NCHUNK * NH * DS * HD];     // [k][h][n][p]
__device__ float g_hid[(size_t)L_TOK * DMODEL];        // tf32-rounded hidden
__device__ float g_w1[(size_t)IN2 * DMODEL];           // tf32-rounded W_in
__device__ float g_w2[(size_t)DMODEL * INNER];         // tf32-rounded W_out
__device__ float g_dt[NH];
__device__ float g_a[NH];

// ---------------- helpers ---------------------------------------------------
__device__ __forceinline__ uint32_t s2u(const void* p) {
    uint32_t a;
    asm("{ .reg .u64 t; cvta.to.shared.u64 t, %1; cvt.u32.u64 %0, t; }"
        : "=r"(a) : "l"(p));
    return a;
}
__device__ __forceinline__ void cpasync16(uint32_t saddr, const void* g) {
    asm volatile("cp.async.cg.shared.global [%0], [%1], 16;" :: "r"(saddr), "l"(g));
}
__device__ __forceinline__ float rtf32(float x) {
    uint32_t r;
    asm("cvt.rna.tf32.f32 %0, %1;" : "=r"(r) : "f"(x));
    return __uint_as_float(r);
}
__device__ __forceinline__ void ffma2(float2 &d, const float2 &a, const float2 &b) {
    unsigned long long ud, ua, ub;
    __builtin_memcpy(&ud, &d, 8);
    __builtin_memcpy(&ua, &a, 8);
    __builtin_memcpy(&ub, &b, 8);
    asm("fma.rn.f32x2 %0, %1, %2, %0;" : "+l"(ud) : "l"(ua), "l"(ub));
    __builtin_memcpy(&d, &ud, 8);
}
__device__ __forceinline__ void ldsm4(uint32_t* r, uint32_t addr) {
    asm volatile("ldmatrix.sync.aligned.m8n8.x4.shared.b16 {%0,%1,%2,%3}, [%4];"
                 : "=r"(r[0]), "=r"(r[1]), "=r"(r[2]), "=r"(r[3]) : "r"(addr));
}
__device__ __forceinline__ void mma16n8k8(float* d, const uint32_t* a,
                                          uint32_t b0, uint32_t b1) {
    asm volatile(
        "mma.sync.aligned.m16n8k8.row.col.f32.tf32.tf32.f32 "
        "{%0,%1,%2,%3}, {%4,%5,%6,%7}, {%8,%9}, {%0,%1,%2,%3};"
        : "+f"(d[0]), "+f"(d[1]), "+f"(d[2]), "+f"(d[3])
        : "r"(a[0]), "r"(a[1]), "r"(a[2]), "r"(a[3]), "r"(b0), "r"(b1));
}

// ---------------- per-head parameters --------------------------------------
__global__ void hparams_kernel(const float* __restrict__ A_log,
                               const float* __restrict__ dt_bias) {
    int h = threadIdx.x;
    if (h < NH) {
        float xv = 0.1f + dt_bias[h];
        float sp = (xv > 20.f) ? xv : log1pf(expf(xv));
        g_dt[h] = sp;
        g_a[h]  = -expf(A_log[h]) * sp;
    }
}

// ---------------- round-to-nearest tf32 preprocessing ----------------------
__global__ void round_tf32_kernel(const float* __restrict__ in, float* __restrict__ out, int n4) {
    int i = blockIdx.x * blockDim.x + threadIdx.x;
    int stride = gridDim.x * blockDim.x;
    for (; i < n4; i += stride) {
        float4 v = ((const float4*)in)[i];
        v.x = rtf32(v.x); v.y = rtf32(v.y); v.z = rtf32(v.z); v.w = rtf32(v.w);
        ((float4*)out)[i] = v;
    }
}

// ---------------- mma.sync TF32 GEMM: C[M,N] = A[M,K]*B[N,K]^T -------------
// (R5 config — best measured) Block 128x256x32; 512 thr = 16 warps 2m x 8n;
// warp tile 64x32; ldmatrix fragments; 4-stage cp.async.
#define KT       32
#define ALD      36
#define A_FLT    (128 * ALD)
#define B_FLT    (256 * ALD)
#define STG_FLT  (A_FLT + B_FLT)
#define STGB     (STG_FLT * 4)
#define NSTG     4
#define GM_SMEM  (NSTG * STGB)               // 221184 B

__global__ __launch_bounds__(512, 1)
void gemm_mma(const float* __restrict__ A, const float* __restrict__ B,
              float* __restrict__ C, int M, int N, int K, int tiles_m) {
    extern __shared__ __align__(16) float sm[];
    uint32_t sbase = s2u(sm);

    int tid = threadIdx.x, lane = tid & 31, wid = tid >> 5;
    int wm = (wid & 1) * 64;
    int wn = (wid >> 1) * 32;
    int bid = blockIdx.x;
    int m0 = (bid % tiles_m) * 128;
    int n0 = (bid / tiles_m) * 256;

    const float* gA[2]; uint32_t oA[2];
    #pragma unroll
    for (int it = 0; it < 2; it++) {
        int q = tid + it * 512;
        int r = q >> 3, c4 = (q & 7) * 4;
        gA[it] = A + (size_t)(m0 + r) * K + c4;
        oA[it] = (uint32_t)(r * ALD + c4) * 4;
    }
    const float* gB[4]; uint32_t oB[4];
    #pragma unroll
    for (int it = 0; it < 4; it++) {
        int q = tid + it * 512;
        int r = q >> 3, c4 = (q & 7) * 4;
        gB[it] = B + (size_t)(n0 + r) * K + c4;
        oB[it] = (uint32_t)(A_FLT + r * ALD + c4) * 4;
    }

    int lr = lane & 7;
    int a_row = lr + ((lane >> 3) & 1) * 8;
    int a_col = ((lane >> 4) & 1) * 4;
    uint32_t aoff[4];
    #pragma unroll
    for (int t = 0; t < 4; t++)
        aoff[t] = sbase + (uint32_t)(((wm + t * 16 + a_row) * ALD + a_col) * 4);
    int b_row = lr + ((lane >> 4) & 1) * 8;
    int b_col = ((lane >> 3) & 1) * 4;
    uint32_t boff[2];
    #pragma unroll
    for (int v = 0; v < 2; v++)
        boff[v] = sbase + (uint32_t)((A_FLT + (wn + v * 16 + b_row) * ALD + b_col) * 4);

    const int NKC = K / KT;

    #pragma unroll
    for (int s = 0; s < NSTG - 1; s++) {
        uint32_t sb = sbase + s * STGB;
        #pragma unroll
        for (int it = 0; it < 2; it++) cpasync16(sb + oA[it], gA[it] + s * KT);
        #pragma unroll
        for (int it = 0; it < 4; it++) cpasync16(sb + oB[it], gB[it] + s * KT);
        asm volatile("cp.async.commit_group;");
    }

    float acc[4][4][4];
    #pragma unroll
    for (int t = 0; t < 4; t++)
        #pragma unroll
        for (int u = 0; u < 4; u++)
            #pragma unroll
            for (int v = 0; v < 4; v++) acc[t][u][v] = 0.f;

    for (int kb = 0; kb < NKC; kb++) {
        int st = kb & (NSTG - 1);
        asm volatile("cp.async.wait_group %0;" :: "n"(NSTG - 2));
        __syncthreads();

        {
            int fc = kb + NSTG - 1;
            if (fc < NKC) {
                uint32_t sb = sbase + (fc & (NSTG - 1)) * STGB;
                #pragma unroll
                for (int it = 0; it < 2; it++) cpasync16(sb + oA[it], gA[it] + fc * KT);
                #pragma unroll
                for (int it = 0; it < 4; it++) cpasync16(sb + oB[it], gB[it] + fc * KT);
            }
            asm volatile("cp.async.commit_group;");
        }

        uint32_t stb = st * STGB;
        #pragma unroll
        for (int ks = 0; ks < 4; ks++) {
            uint32_t kadd = stb + ks * 32;
            uint32_t af[4][4];
            #pragma unroll
            for (int t = 0; t < 4; t++) ldsm4(af[t], aoff[t] + kadd);
            uint32_t bf[2][4];
            #pragma unroll
            for (int v = 0; v < 2; v++) ldsm4(bf[v], boff[v] + kadd);
            #pragma unroll
            for (int u = 0; u < 4; u++) {
                uint32_t b0 = bf[u >> 1][(u & 1) * 2 + 0];
                uint32_t b1 = bf[u >> 1][(u & 1) * 2 + 1];
                #pragma unroll
                for (int t = 0; t < 4; t++) mma16n8k8(acc[t][u], af[t], b0, b1);
            }
        }
    }

    int g4 = lane >> 2, c4i = lane & 3;
    #pragma unroll
    for (int t = 0; t < 4; t++) {
        int r0 = m0 + wm + t * 16 + g4;
        #pragma unroll
        for (int u = 0; u < 4; u++) {
            int col = n0 + wn + u * 8 + c4i * 2;
            *(float2*)&C[(size_t)r0 * N + col] = make_float2(acc[t][u][0], acc[t][u][1]);
            *(float2*)&C[(size_t)(r0 + 8) * N + col] = make_float2(acc[t][u][2], acc[t][u][3]);
        }
    }
}

// ---------------- per-chunk end states: S[k,h,p,n] --------------------------
__global__ void states_kernel(const float* __restrict__ Bin) {
    int k = blockIdx.x, h = blockIdx.y;
    int tid = threadIdx.x;
    int p = tid & 63, quad = tid >> 6;
    float a = g_a[h], dtv = g_dt[h];
    int g = h / HPG;
    __shared__ float sx[8 * 64], sbuf[8 * 64];
    float acc[16];
    #pragma unroll
    for (int m = 0; m < 16; m++) acc[m] = 0.f;
    int lb = k * CHUNKSZ;
    for (int jb = 0; jb < CHUNKSZ; jb += 8) {
        __syncthreads();
        #pragma unroll
        for (int it = 0; it < 2; it++) {
            int e = tid + it * 256;
            int jj = e >> 6, pp = e & 63;
            int l = lb + jb + jj;
            sx[e] = g_xz[(size_t)l * IN2 + h * HD + pp];
            sbuf[e] = Bin[((size_t)l * NG + g) * DS + pp];
        }
        __syncthreads();
        #pragma unroll
        for (int jj = 0; jj < 8; jj++) {
            int j = jb + jj;
            float dec = expf(a * (float)(CHUNKSZ - 1 - j)) * dtv;
            float v = sx[jj * 64 + p] * dec;
            #pragma unroll
            for (int m = 0; m < 16; m++)
                acc[m] += v * sbuf[jj * 64 + quad + 4 * m];
        }
    }
    size_t base = ((size_t)(k * NH + h)) << 12;
    #pragma unroll
    for (int m = 0; m < 16; m++)
        g_states[base + p * 64 + quad + 4 * m] = acc[m];
}

// ---------------- inter-chunk scan -----------------------------------------
__global__ void scan_kernel() {
    int h = blockIdx.x;
    float cd = expf(g_a[h] * (float)CHUNKSZ);
    for (int e = threadIdx.x; e < HD * DS; e += 256) {
        int p = e >> 6, n = e & 63;
        float carry = 0.f;
        #pragma unroll
        for (int k = 0; k < NCHUNK; k++) {
            size_t base = ((size_t)(k * NH + h)) << 12;
            g_prev[base + n * 64 + p] = carry;
            carry = carry * cd + g_states[base + e];
        }
    }
}

// ---------------- intra-chunk + off-diagonal + gate -------------------------
// One block per (chunk k, head-pair). B/C tiles are group-shared -> loaded
// once for both heads. 256 threads: hs = tid>>7 selects head, 128 rows each.
// SMSP balance: head0 warp w -> rows 32w.., head1 warp w -> rows 32(3-w)..
#define CLD 65
// floats: sB 128*64, sC 128*CLD, sX 2*128*64, sP 2*64*64, sDec 2*132
#define SY_FLOATS (128*64 + 128*CLD + 2*128*64 + 2*64*64 + 2*132)
__global__ __launch_bounds__(256, 1)
void yblock_kernel(const float* __restrict__ Bin, const float* __restrict__ Cin,
                   const float* __restrict__ Dv) {
    extern __shared__ float sm[];
    float* sB   = sm;                          // [128][64]
    float* sC   = sB + 128 * 64;               // [128][CLD]
    float* sX   = sC + 128 * CLD;              // [2][128][64]
    float* sP   = sX + 2 * 128 * 64;           // [2][64][64]
    float* sDec = sP + 2 * 64 * 64;            // [2][132]

    int k = blockIdx.x;
    int h0 = blockIdx.y * 2;
    int tid = threadIdx.x;
    int lane = tid & 31;
    int hs = tid >> 7;                         // which head of the pair
    int wh = (tid >> 5) & 3;                   // warp within head-half
    int h = h0 + hs;
    float a = g_a[h], dtv = g_dt[h], Dh = Dv[h];
    int g = h0 / HPG;
    int lb = k * CHUNKSZ;

    // ---- loads ----
    float4* sB4 = (float4*)sB;
    float4* sX4 = (float4*)sX;
    float4* sP4 = (float4*)sP;
    #pragma unroll
    for (int it = 0; it < 8; it++) {           // B: 2048 float4
        int q = tid + it * 256;
        int j = q >> 4, p4 = q & 15;
        sB4[q] = *(const float4*)&Bin[((size_t)(lb + j) * NG + g) * DS + p4 * 4];
    }
    #pragma unroll
    for (int it = 0; it < 16; it++) {          // X: 2 heads x 2048 float4
        int q = tid + it * 256;
        int hh = q >> 11, rem = q & 2047;
        int j = rem >> 4, p4 = rem & 15;
        sX4[q] = *(const float4*)&g_xz[(size_t)(lb + j) * IN2 + (h0 + hh) * HD + p4 * 4];
    }
    #pragma unroll
    for (int it = 0; it < 8; it++) {           // prev: 2 heads x 1024 float4
        int q = tid + it * 256;
        int hh = q >> 10, rem = q & 1023;
        size_t pbase = ((size_t)(k * NH + h0 + hh)) << 12;
        sP4[q] = *(const float4*)&g_prev[pbase + (size_t)rem * 4];
    }
    {
        int wtid = tid & 127;
        for (int d = wtid; d < CHUNKSZ + 2; d += 128)
            sDec[hs * 132 + d] = expf(a * (float)d);
    }

    // balanced row assignment
    int rg = hs ? (3 - wh) : wh;
    int i = rg * 32 + lane;

    // own C row -> registers; head0 half also writes the shared sC tile
    float2 cre2[32];
    {
        const float4* Crow = (const float4*)&Cin[((size_t)(lb + i) * NG + g) * DS];
        #pragma unroll
        for (int n4 = 0; n4 < 16; n4++) {
            float4 v = Crow[n4];
            cre2[2 * n4 + 0] = make_float2(v.x, v.y);
            cre2[2 * n4 + 1] = make_float2(v.z, v.w);
            if (hs == 0) {
                sC[i * CLD + 4 * n4 + 0] = v.x;
                sC[i * CLD + 4 * n4 + 1] = v.y;
                sC[i * CLD + 4 * n4 + 2] = v.z;
                sC[i * CLD + 4 * n4 + 3] = v.w;
            }
        }
    }
    __syncthreads();

    const float* sXh = sX + hs * (128 * 64);
    const float* sPh = sP + hs * (64 * 64);
    const float* sDh = sDec + hs * 132;

    float2 acc2[32];
    #pragma unroll
    for (int p = 0; p < 32; p++) acc2[p] = make_float2(0.f, 0.f);

    // 1) intra-chunk triangle
    for (int j = 0; j <= i; j++) {
        const float4* bj = (const float4*)&sB[j * 64];
        float2 s2 = make_float2(0.f, 0.f);
        #pragma unroll
        for (int m4 = 0; m4 < 16; m4++) {
            float4 bv = bj[m4];
            ffma2(s2, cre2[2 * m4 + 0], make_float2(bv.x, bv.y));
            ffma2(s2, cre2[2 * m4 + 1], make_float2(bv.z, bv.w));
        }
        float w = (s2.x + s2.y) * sDh[i - j] * dtv;
        float2 w2 = make_float2(w, w);
        const float4* xj = (const float4*)&sXh[j * 64];
        #pragma unroll
        for (int p4 = 0; p4 < 16; p4++) {
            float4 xv = xj[p4];
            ffma2(acc2[2 * p4 + 0], w2, make_float2(xv.x, xv.y));
            ffma2(acc2[2 * p4 + 1], w2, make_float2(xv.z, xv.w));
        }
    }

    // 2) off-diagonal
    {
        float coef = sDh[i + 1];
        for (int n = 0; n < 64; n++) {
            float w = sC[i * CLD + n] * coef;
            float2 w2 = make_float2(w, w);
            const float4* pn = (const float4*)&sPh[n * 64];
            #pragma unroll
            for (int p4 = 0; p4 < 16; p4++) {
                float4 pv = pn[p4];
                ffma2(acc2[2 * p4 + 0], w2, make_float2(pv.x, pv.y));
                ffma2(acc2[2 * p4 + 1], w2, make_float2(pv.z, pv.w));
            }
        }
    }

    // 3) + x*D, gate with sigmoid(z), round to tf32, store
    {
        int l = lb + i;
        const float* zrow = &g_xz[(size_t)l * IN2 + INNER + h * HD];
        const float* xrow = &sXh[i * 64];
        float* outp = &g_yg[(size_t)l * INNER + h * HD];
        #pragma unroll
        for (int p4 = 0; p4 < 16; p4++) {
            float4 zv = *(const float4*)&zrow[p4 * 4];
            float4 xv = *(const float4*)&xrow[p4 * 4];
            float4 o;
            o.x = rtf32((acc2[2 * p4 + 0].x + xv.x * Dh) / (1.f + expf(-zv.x)));
            o.y = rtf32((acc2[2 * p4 + 0].y + xv.y * Dh) / (1.f + expf(-zv.y)));
            o.z = rtf32((acc2[2 * p4 + 1].x + xv.z * Dh) / (1.f + expf(-zv.z)));
            o.w = rtf32((acc2[2 * p4 + 1].y + xv.w * Dh) / (1.f + expf(-zv.w)));
            *(float4*)&outp[p4 * 4] = o;
        }
    }
}

// ---------------- launcher --------------------------------------------------
extern "C" void kernel_launch(void* const* d_in, const int* in_sizes, int n_in,
                              void* d_out, int out_size) {
    (void)in_sizes; (void)n_in; (void)out_size;
    const float* hidden = (const float*)d_in[0];
    const float* W_in   = (const float*)d_in[1];
    const float* W_out  = (const float*)d_in[2];
    const float* A_log  = (const float*)d_in[3];
    const float* Dv     = (const float*)d_in[4];
    const float* dtb    = (const float*)d_in[5];
    const float* Bin    = (const float*)d_in[6];
    const float* Cin    = (const float*)d_in[7];
    float* out = (float*)d_out;

    float *xz_ptr, *yg_ptr, *hid_ptr, *w1_ptr, *w2_ptr;
    cudaGetSymbolAddress((void**)&xz_ptr, g_xz);
    cudaGetSymbolAddress((void**)&yg_ptr, g_yg);
    cudaGetSymbolAddress((void**)&hid_ptr, g_hid);
    cudaGetSymbolAddress((void**)&w1_ptr, g_w1);
    cudaGetSymbolAddress((void**)&w2_ptr, g_w2);

    cudaFuncSetAttribute(gemm_mma, cudaFuncAttributeMaxDynamicSharedMemorySize, GM_SMEM);

    // launch order chosen so gemm1 is the 4th launch (ncu captures it)
    hparams_kernel<<<1, 128>>>(A_log, dtb);                                   // 1
    round_tf32_kernel<<<1184, 256>>>(W_in,   w1_ptr,  (IN2 * DMODEL) / 4);    // 2
    round_tf32_kernel<<<1184, 256>>>(hidden, hid_ptr, (L_TOK * DMODEL) / 4);  // 3

    // GEMM1: xz[L, IN2] = hid[L, DMODEL] @ W_in[IN2, DMODEL]^T
    {
        int tiles_m = L_TOK / 128;      // 32
        int tiles_n = IN2 / 256;        // 56
        gemm_mma<<<tiles_m * tiles_n, 512, GM_SMEM>>>(hid_ptr, w1_ptr, xz_ptr,
                                                      L_TOK, IN2, DMODEL, tiles_m);  // 4
    }

    states_kernel<<<dim3(NCHUNK, NH), 256>>>(Bin);                            // 5
    scan_kernel<<<NH, 256>>>();                                               // 6

    {
        size_t smem = (size_t)SY_FLOATS * sizeof(float);   // ~166 KB
        cudaFuncSetAttribute(yblock_kernel,
                             cudaFuncAttributeMaxDynamicSharedMemorySize, (int)smem);
        yblock_kernel<<<dim3(NCHUNK, NH / 2), 256, smem>>>(Bin, Cin, Dv);     // 7
    }

    round_tf32_kernel<<<1184, 256>>>(W_out, w2_ptr, (DMODEL * INNER) / 4);    // 8

    // GEMM2: out[L, DMODEL] = yg[L, INNER] @ W_out[DMODEL, INNER]^T
    {
        int tiles_m = L_TOK / 128;      // 32
        int tiles_n = DMODEL / 256;     // 14
        gemm_mma<<<tiles_m * tiles_n, 512, GM_SMEM>>>(yg_ptr, w2_ptr, out,
                                                      L_TOK, DMODEL, INNER, tiles_m); // 9
    }
}

// round 8
// speedup vs baseline: 1.6819x; 1.5538x over previous
#include <cuda_runtime.h>
#include <cuda_fp16.h>
#include <math.h>
#include <stdint.h>

// ---------------- problem constants ----------------
#define L_TOK   4096
#define DMODEL  3584
#define NH      112
#define HD      64
#define DS      64
#define CHUNKSZ 128
#define NCHUNK  32
#define NG      2
#define HPG     (NH / NG)          // 56
#define INNER   (NH * HD)          // 7168
#define IN2     (2 * INNER)        // 14336

// ---------------- scratch (device globals; no cudaMalloc allowed) ----------
__device__ float  g_xz[(size_t)L_TOK * IN2];           // [x | z]  (fp32)
__device__ __half g_ygh[(size_t)L_TOK * INNER];        // gated y  (fp16)
__device__ float  g_states[(size_t)NCHUNK * NH * HD * DS];  // [k][h][p][n]
__device__ float  g_prev[(size_t)NCHUNK * NH * DS * HD];    // [k][h][n][p]
__device__ __half g_hidh[(size_t)L_TOK * DMODEL];      // fp16 hidden
__device__ __half g_w1h[(size_t)IN2 * DMODEL];         // fp16 W_in
__device__ __half g_w2h[(size_t)DMODEL * INNER];       // fp16 W_out
__device__ float  g_dt[NH];
__device__ float  g_a[NH];

// ---------------- helpers ---------------------------------------------------
__device__ __forceinline__ uint32_t s2u(const void* p) {
    uint32_t a;
    asm("{ .reg .u64 t; cvta.to.shared.u64 t, %1; cvt.u32.u64 %0, t; }"
        : "=r"(a) : "l"(p));
    return a;
}
__device__ __forceinline__ void cpasync16(uint32_t saddr, const void* g) {
    asm volatile("cp.async.cg.shared.global [%0], [%1], 16;" :: "r"(saddr), "l"(g));
}
__device__ __forceinline__ void ffma2(float2 &d, const float2 &a, const float2 &b) {
    unsigned long long ud, ua, ub;
    __builtin_memcpy(&ud, &d, 8);
    __builtin_memcpy(&ua, &a, 8);
    __builtin_memcpy(&ub, &b, 8);
    asm("fma.rn.f32x2 %0, %1, %2, %0;" : "+l"(ud) : "l"(ua), "l"(ub));
    __builtin_memcpy(&d, &ud, 8);
}
__device__ __forceinline__ void ldsm4(uint32_t* r, uint32_t addr) {
    asm volatile("ldmatrix.sync.aligned.m8n8.x4.shared.b16 {%0,%1,%2,%3}, [%4];"
                 : "=r"(r[0]), "=r"(r[1]), "=r"(r[2]), "=r"(r[3]) : "r"(addr));
}
// m16n8k16 fp16 mma, fp32 accumulate (sm_80 baseline PTX)
__device__ __forceinline__ void mma16n8k16(float* d, const uint32_t* a,
                                           uint32_t b0, uint32_t b1) {
    asm volatile(
        "mma.sync.aligned.m16n8k16.row.col.f32.f16.f16.f32 "
        "{%0,%1,%2,%3}, {%4,%5,%6,%7}, {%8,%9}, {%0,%1,%2,%3};"
        : "+f"(d[0]), "+f"(d[1]), "+f"(d[2]), "+f"(d[3])
        : "r"(a[0]), "r"(a[1]), "r"(a[2]), "r"(a[3]), "r"(b0), "r"(b1));
}
__device__ __forceinline__ uint32_t pack_h2(float lo, float hi) {
    uint32_t r;
    asm("cvt.rn.f16x2.f32 %0, %1, %2;" : "=r"(r) : "f"(hi), "f"(lo));
    return r;
}

// ---------------- per-head parameters --------------------------------------
__global__ void hparams_kernel(const float* __restrict__ A_log,
                               const float* __restrict__ dt_bias) {
    int h = threadIdx.x;
    if (h < NH) {
        float xv = 0.1f + dt_bias[h];
        float sp = (xv > 20.f) ? xv : log1pf(expf(xv));
        g_dt[h] = sp;
        g_a[h]  = -expf(A_log[h]) * sp;
    }
}

// ---------------- fp32 -> fp16 conversion ----------------------------------
__global__ void to_half_kernel(const float* __restrict__ in, __half* __restrict__ out, int n8) {
    int i = blockIdx.x * blockDim.x + threadIdx.x;
    int stride = gridDim.x * blockDim.x;
    for (; i < n8; i += stride) {
        float4 a = ((const float4*)in)[2 * i];
        float4 b = ((const float4*)in)[2 * i + 1];
        uint4 o;
        o.x = pack_h2(a.x, a.y);
        o.y = pack_h2(a.z, a.w);
        o.z = pack_h2(b.x, b.y);
        o.w = pack_h2(b.z, b.w);
        ((uint4*)out)[i] = o;
    }
}

// ---------------- mma.sync FP16 GEMM: C[M,N] = A[M,K]*B[N,K]^T -------------
// Block 128(M) x 256(N) x 64(K halfs); 512 thr = 16 warps 2m x 8n;
// warp tile 64x32; ldmatrix b16 fragments; 4-stage cp.async.
#define KTH      64
#define ALDH     72                          // halfs; 144B stride, conflict-free
#define A_H      (128 * ALDH)                // halfs / stage
#define B_H      (256 * ALDH)
#define STGB     ((A_H + B_H) * 2)           // 55296 B
#define NSTG     4
#define GM_SMEM  (NSTG * STGB)               // 221184 B

__global__ __launch_bounds__(512, 1)
void gemm_mma(const __half* __restrict__ A, const __half* __restrict__ B,
              float* __restrict__ C, int M, int N, int K, int tiles_m) {
    extern __shared__ __align__(16) char smraw[];
    uint32_t sbase = s2u(smraw);

    int tid = threadIdx.x, lane = tid & 31, wid = tid >> 5;
    int wm = (wid & 1) * 64;
    int wn = (wid >> 1) * 32;
    int bid = blockIdx.x;
    int m0 = (bid % tiles_m) * 128;
    int n0 = (bid / tiles_m) * 256;

    // cp.async: A tile 128x64 halfs = 1024 16B-loads (2/thread); B 2048 (4/thread)
    const __half* gA[2]; uint32_t oA[2];
    #pragma unroll
    for (int it = 0; it < 2; it++) {
        int q = tid + it * 512;
        int r = q >> 3, c8 = (q & 7) * 8;
        gA[it] = A + (size_t)(m0 + r) * K + c8;
        oA[it] = (uint32_t)(r * ALDH + c8) * 2;
    }
    const __half* gB[4]; uint32_t oB[4];
    #pragma unroll
    for (int it = 0; it < 4; it++) {
        int q = tid + it * 512;
        int r = q >> 3, c8 = (q & 7) * 8;
        gB[it] = B + (size_t)(n0 + r) * K + c8;
        oB[it] = (uint32_t)(A_H + r * ALDH + c8) * 2;
    }

    // ldmatrix per-lane addresses (offsets in halfs; k-step offset added per ks)
    int lr = lane & 7;
    int a_row = lr + ((lane >> 3) & 1) * 8;
    int a_col = ((lane >> 4) & 1) * 8;
    uint32_t aoff[4];
    #pragma unroll
    for (int t = 0; t < 4; t++)
        aoff[t] = sbase + (uint32_t)(((wm + t * 16 + a_row) * ALDH + a_col) * 2);
    int b_row = lr + ((lane >> 4) & 1) * 8;
    int b_col = ((lane >> 3) & 1) * 8;
    uint32_t boff[2];
    #pragma unroll
    for (int v = 0; v < 2; v++)
        boff[v] = sbase + (uint32_t)((A_H + (wn + v * 16 + b_row) * ALDH + b_col) * 2);

    const int NKC = K / KTH;

    #pragma unroll
    for (int s = 0; s < NSTG - 1; s++) {
        uint32_t sb = sbase + s * STGB;
        #pragma unroll
        for (int it = 0; it < 2; it++) cpasync16(sb + oA[it], gA[it] + s * KTH);
        #pragma unroll
        for (int it = 0; it < 4; it++) cpasync16(sb + oB[it], gB[it] + s * KTH);
        asm volatile("cp.async.commit_group;");
    }

    float acc[4][4][4];
    #pragma unroll
    for (int t = 0; t < 4; t++)
        #pragma unroll
        for (int u = 0; u < 4; u++)
            #pragma unroll
            for (int v = 0; v < 4; v++) acc[t][u][v] = 0.f;

    for (int kb = 0; kb < NKC; kb++) {
        int st = kb & (NSTG - 1);
        asm volatile("cp.async.wait_group %0;" :: "n"(NSTG - 2));
        __syncthreads();

        {
            int fc = kb + NSTG - 1;
            if (fc < NKC) {
                uint32_t sb = sbase + (fc & (NSTG - 1)) * STGB;
                #pragma unroll
                for (int it = 0; it < 2; it++) cpasync16(sb + oA[it], gA[it] + fc * KTH);
                #pragma unroll
                for (int it = 0; it < 4; it++) cpasync16(sb + oB[it], gB[it] + fc * KTH);
            }
            asm volatile("cp.async.commit_group;");
        }

        uint32_t stb = st * STGB;
        #pragma unroll
        for (int ks = 0; ks < 4; ks++) {
            uint32_t kadd = stb + ks * 32;          // 16 halfs = 32 bytes per k-step
            uint32_t af[4][4];
            #pragma unroll
            for (int t = 0; t < 4; t++) ldsm4(af[t], aoff[t] + kadd);
            uint32_t bf[2][4];
            #pragma unroll
            for (int v = 0; v < 2; v++) ldsm4(bf[v], boff[v] + kadd);
            #pragma unroll
            for (int u = 0; u < 4; u++) {
                uint32_t b0 = bf[u >> 1][(u & 1) * 2 + 0];
                uint32_t b1 = bf[u >> 1][(u & 1) * 2 + 1];
                #pragma unroll
                for (int t = 0; t < 4; t++) mma16n8k16(acc[t][u], af[t], b0, b1);
            }
        }
    }

    int g4 = lane >> 2, c4i = lane & 3;
    #pragma unroll
    for (int t = 0; t < 4; t++) {
        int r0 = m0 + wm + t * 16 + g4;
        #pragma unroll
        for (int u = 0; u < 4; u++) {
            int col = n0 + wn + u * 8 + c4i * 2;
            *(float2*)&C[(size_t)r0 * N + col] = make_float2(acc[t][u][0], acc[t][u][1]);
            *(float2*)&C[(size_t)(r0 + 8) * N + col] = make_float2(acc[t][u][2], acc[t][u][3]);
        }
    }
}

// ---------------- per-chunk end states: S[k,h,p,n] --------------------------
__global__ void states_kernel(const float* __restrict__ Bin) {
    int k = blockIdx.x, h = blockIdx.y;
    int tid = threadIdx.x;
    int p = tid & 63, quad = tid >> 6;
    float a = g_a[h], dtv = g_dt[h];
    int g = h / HPG;
    __shared__ float sx[8 * 64], sbuf[8 * 64];
    float acc[16];
    #pragma unroll
    for (int m = 0; m < 16; m++) acc[m] = 0.f;
    int lb = k * CHUNKSZ;
    for (int jb = 0; jb < CHUNKSZ; jb += 8) {
        __syncthreads();
        #pragma unroll
        for (int it = 0; it < 2; it++) {
            int e = tid + it * 256;
            int jj = e >> 6, pp = e & 63;
            int l = lb + jb + jj;
            sx[e] = g_xz[(size_t)l * IN2 + h * HD + pp];
            sbuf[e] = Bin[((size_t)l * NG + g) * DS + pp];
        }
        __syncthreads();
        #pragma unroll
        for (int jj = 0; jj < 8; jj++) {
            int j = jb + jj;
            float dec = expf(a * (float)(CHUNKSZ - 1 - j)) * dtv;
            float v = sx[jj * 64 + p] * dec;
            #pragma unroll
            for (int m = 0; m < 16; m++)
                acc[m] += v * sbuf[jj * 64 + quad + 4 * m];
        }
    }
    size_t base = ((size_t)(k * NH + h)) << 12;
    #pragma unroll
    for (int m = 0; m < 16; m++)
        g_states[base + p * 64 + quad + 4 * m] = acc[m];
}

// ---------------- inter-chunk scan -----------------------------------------
__global__ void scan_kernel() {
    int h = blockIdx.x;
    float cd = expf(g_a[h] * (float)CHUNKSZ);
    for (int e = threadIdx.x; e < HD * DS; e += 256) {
        int p = e >> 6, n = e & 63;
        float carry = 0.f;
        #pragma unroll
        for (int k = 0; k < NCHUNK; k++) {
            size_t base = ((size_t)(k * NH + h)) << 12;
            g_prev[base + n * 64 + p] = carry;
            carry = carry * cd + g_states[base + e];
        }
    }
}

// ---------------- intra-chunk + off-diagonal + gate -------------------------
// One block per (chunk k, head-pair). B/C group-shared. 256 threads: 2 heads
// x 128 rows. SMSP balance via warp remap.
#define CLD 65
#define SY_FLOATS (128*64 + 128*CLD + 2*128*64 + 2*64*64 + 2*132)
__global__ __launch_bounds__(256, 1)
void yblock_kernel(const float* __restrict__ Bin, const float* __restrict__ Cin,
                   const float* __restrict__ Dv) {
    extern __shared__ float sm[];
    float* sB   = sm;
    float* sC   = sB + 128 * 64;
    float* sX   = sC + 128 * CLD;
    float* sP   = sX + 2 * 128 * 64;
    float* sDec = sP + 2 * 64 * 64;

    int k = blockIdx.x;
    int h0 = blockIdx.y * 2;
    int tid = threadIdx.x;
    int lane = tid & 31;
    int hs = tid >> 7;
    int wh = (tid >> 5) & 3;
    int h = h0 + hs;
    float a = g_a[h], dtv = g_dt[h], Dh = Dv[h];
    int g = h0 / HPG;
    int lb = k * CHUNKSZ;

    float4* sB4 = (float4*)sB;
    float4* sX4 = (float4*)sX;
    float4* sP4 = (float4*)sP;
    #pragma unroll
    for (int it = 0; it < 8; it++) {
        int q = tid + it * 256;
        int j = q >> 4, p4 = q & 15;
        sB4[q] = *(const float4*)&Bin[((size_t)(lb + j) * NG + g) * DS + p4 * 4];
    }
    #pragma unroll
    for (int it = 0; it < 16; it++) {
        int q = tid + it * 256;
        int hh = q >> 11, rem = q & 2047;
        int j = rem >> 4, p4 = rem & 15;
        sX4[q] = *(const float4*)&g_xz[(size_t)(lb + j) * IN2 + (h0 + hh) * HD + p4 * 4];
    }
    #pragma unroll
    for (int it = 0; it < 8; it++) {
        int q = tid + it * 256;
        int hh = q >> 10, rem = q & 1023;
        size_t pbase = ((size_t)(k * NH + h0 + hh)) << 12;
        sP4[q] = *(const float4*)&g_prev[pbase + (size_t)rem * 4];
    }
    {
        int wtid = tid & 127;
        for (int d = wtid; d < CHUNKSZ + 2; d += 128)
            sDec[hs * 132 + d] = expf(a * (float)d);
    }

    int rg = hs ? (3 - wh) : wh;
    int i = rg * 32 + lane;

    float2 cre2[32];
    {
        const float4* Crow = (const float4*)&Cin[((size_t)(lb + i) * NG + g) * DS];
        #pragma unroll
        for (int n4 = 0; n4 < 16; n4++) {
            float4 v = Crow[n4];
            cre2[2 * n4 + 0] = make_float2(v.x, v.y);
            cre2[2 * n4 + 1] = make_float2(v.z, v.w);
            if (hs == 0) {
                sC[i * CLD + 4 * n4 + 0] = v.x;
                sC[i * CLD + 4 * n4 + 1] = v.y;
                sC[i * CLD + 4 * n4 + 2] = v.z;
                sC[i * CLD + 4 * n4 + 3] = v.w;
            }
        }
    }
    __syncthreads();

    const float* sXh = sX + hs * (128 * 64);
    const float* sPh = sP + hs * (64 * 64);
    const float* sDh = sDec + hs * 132;

    float2 acc2[32];
    #pragma unroll
    for (int p = 0; p < 32; p++) acc2[p] = make_float2(0.f, 0.f);

    for (int j = 0; j <= i; j++) {
        const float4* bj = (const float4*)&sB[j * 64];
        float2 s2 = make_float2(0.f, 0.f);
        #pragma unroll
        for (int m4 = 0; m4 < 16; m4++) {
            float4 bv = bj[m4];
            ffma2(s2, cre2[2 * m4 + 0], make_float2(bv.x, bv.y));
            ffma2(s2, cre2[2 * m4 + 1], make_float2(bv.z, bv.w));
        }
        float w = (s2.x + s2.y) * sDh[i - j] * dtv;
        float2 w2 = make_float2(w, w);
        const float4* xj = (const float4*)&sXh[j * 64];
        #pragma unroll
        for (int p4 = 0; p4 < 16; p4++) {
            float4 xv = xj[p4];
            ffma2(acc2[2 * p4 + 0], w2, make_float2(xv.x, xv.y));
            ffma2(acc2[2 * p4 + 1], w2, make_float2(xv.z, xv.w));
        }
    }
    {
        float coef = sDh[i + 1];
        for (int n = 0; n < 64; n++) {
            float w = sC[i * CLD + n] * coef;
            float2 w2 = make_float2(w, w);
            const float4* pn = (const float4*)&sPh[n * 64];
            #pragma unroll
            for (int p4 = 0; p4 < 16; p4++) {
                float4 pv = pn[p4];
                ffma2(acc2[2 * p4 + 0], w2, make_float2(pv.x, pv.y));
                ffma2(acc2[2 * p4 + 1], w2, make_float2(pv.z, pv.w));
            }
        }
    }
    {
        int l = lb + i;
        const float* zrow = &g_xz[(size_t)l * IN2 + INNER + h * HD];
        const float* xrow = &sXh[i * 64];
        __half* outp = &g_ygh[(size_t)l * INNER + h * HD];
        #pragma unroll
        for (int p4 = 0; p4 < 16; p4++) {
            float4 zv = *(const float4*)&zrow[p4 * 4];
            float4 xv = *(const float4*)&xrow[p4 * 4];
            float y0 = (acc2[2 * p4 + 0].x + xv.x * Dh) / (1.f + expf(-zv.x));
            float y1 = (acc2[2 * p4 + 0].y + xv.y * Dh) / (1.f + expf(-zv.y));
            float y2 = (acc2[2 * p4 + 1].x + xv.z * Dh) / (1.f + expf(-zv.z));
            float y3 = (acc2[2 * p4 + 1].y + xv.w * Dh) / (1.f + expf(-zv.w));
            uint2 o;
            o.x = pack_h2(y0, y1);
            o.y = pack_h2(y2, y3);
            *(uint2*)&outp[p4 * 4] = o;
        }
    }
}

// ---------------- launcher --------------------------------------------------
extern "C" void kernel_launch(void* const* d_in, const int* in_sizes, int n_in,
                              void* d_out, int out_size) {
    (void)in_sizes; (void)n_in; (void)out_size;
    const float* hidden = (const float*)d_in[0];
    const float* W_in   = (const float*)d_in[1];
    const float* W_out  = (const float*)d_in[2];
    const float* A_log  = (const float*)d_in[3];
    const float* Dv     = (const float*)d_in[4];
    const float* dtb    = (const float*)d_in[5];
    const float* Bin    = (const float*)d_in[6];
    const float* Cin    = (const float*)d_in[7];
    float* out = (float*)d_out;

    float *xz_ptr;
    __half *ygh_ptr, *hidh_ptr, *w1h_ptr, *w2h_ptr;
    cudaGetSymbolAddress((void**)&xz_ptr, g_xz);
    cudaGetSymbolAddress((void**)&ygh_ptr, g_ygh);
    cudaGetSymbolAddress((void**)&hidh_ptr, g_hidh);
    cudaGetSymbolAddress((void**)&w1h_ptr, g_w1h);
    cudaGetSymbolAddress((void**)&w2h_ptr, g_w2h);

    cudaFuncSetAttribute(gemm_mma, cudaFuncAttributeMaxDynamicSharedMemorySize, GM_SMEM);

    // launch order: gemm1 is 4th (ncu captures it)
    hparams_kernel<<<1, 128>>>(A_log, dtb);                                   // 1
    to_half_kernel<<<1184, 256>>>(W_in,   w1h_ptr,  (IN2 * DMODEL) / 8);      // 2
    to_half_kernel<<<1184, 256>>>(hidden, hidh_ptr, (L_TOK * DMODEL) / 8);    // 3

    // GEMM1: xz[L, IN2] = hid[L, DMODEL] @ W_in[IN2, DMODEL]^T
    {
        int tiles_m = L_TOK / 128;      // 32
        int tiles_n = IN2 / 256;        // 56
        gemm_mma<<<tiles_m * tiles_n, 512, GM_SMEM>>>(hidh_ptr, w1h_ptr, xz_ptr,
                                                      L_TOK, IN2, DMODEL, tiles_m);  // 4
    }

    states_kernel<<<dim3(NCHUNK, NH), 256>>>(Bin);                            // 5
    scan_kernel<<<NH, 256>>>();                                               // 6

    {
        size_t smem = (size_t)SY_FLOATS * sizeof(float);   // ~166 KB
        cudaFuncSetAttribute(yblock_kernel,
                             cudaFuncAttributeMaxDynamicSharedMemorySize, (int)smem);
        yblock_kernel<<<dim3(NCHUNK, NH / 2), 256, smem>>>(Bin, Cin, Dv);     // 7
    }

    to_half_kernel<<<1184, 256>>>(W_out, w2h_ptr, (DMODEL * INNER) / 8);      // 8

    // GEMM2: out[L, DMODEL] = yg[L, INNER] @ W_out[DMODEL, INNER]^T
    {
        int tiles_m = L_TOK / 128;      // 32
        int tiles_n = DMODEL / 256;     // 14
        gemm_mma<<<tiles_m * tiles_n, 512, GM_SMEM>>>(ygh_ptr, w2h_ptr, out,
                                                      L_TOK, DMODEL, INNER, tiles_m); // 9
    }
}

// round 10
// speedup vs baseline: 1.9373x; 1.1519x over previous
#include <cuda_runtime.h>
#include <cuda_fp16.h>
#include <math.h>
#include <stdint.h>

// ---------------- problem constants ----------------
#define L_TOK   4096
#define DMODEL  3584
#define NH      112
#define HD      64
#define DS      64
#define CHUNKSZ 128
#define NCHUNK  32
#define NG      2
#define HPG     (NH / NG)          // 56
#define INNER   (NH * HD)          // 7168
#define IN2     (2 * INNER)        // 14336

// ---------------- scratch (device globals; no cudaMalloc allowed) ----------
__device__ float  g_xz[(size_t)L_TOK * IN2];           // [x | z]  (fp32)
__device__ __half g_ygh[(size_t)L_TOK * INNER];        // gated y  (fp16)
__device__ float  g_states[(size_t)NCHUNK * NH * HD * DS];  // [k][h][p][n]
__device__ __align__(16) __half g_prevh[(size_t)NCHUNK * NH * HD * DS]; // [k][h][p][n] fp16
__device__ __align__(16) __half g_G[(size_t)NCHUNK * NG * CHUNKSZ * CHUNKSZ]; // C.B^T per (k,g)
__device__ __half g_hidh[(size_t)L_TOK * DMODEL];      // fp16 hidden
__device__ __half g_w1h[(size_t)IN2 * DMODEL];         // fp16 W_in
__device__ __half g_w2h[(size_t)DMODEL * INNER];       // fp16 W_out
__device__ __half g_Bh[(size_t)L_TOK * NG * DS];       // fp16 B
__device__ __half g_Ch[(size_t)L_TOK * NG * DS];       // fp16 C
__device__ float  g_dt[NH];
__device__ float  g_a[NH];

// ---------------- helpers ---------------------------------------------------
__device__ __forceinline__ uint32_t s2u(const void* p) {
    uint32_t a;
    asm("{ .reg .u64 t; cvta.to.shared.u64 t, %1; cvt.u32.u64 %0, t; }"
        : "=r"(a) : "l"(p));
    return a;
}
__device__ __forceinline__ void cpasync16(uint32_t saddr, const void* g) {
    asm volatile("cp.async.cg.shared.global [%0], [%1], 16;" :: "r"(saddr), "l"(g));
}
__device__ __forceinline__ void ldsm4(uint32_t* r, uint32_t addr) {
    asm volatile("ldmatrix.sync.aligned.m8n8.x4.shared.b16 {%0,%1,%2,%3}, [%4];"
                 : "=r"(r[0]), "=r"(r[1]), "=r"(r[2]), "=r"(r[3]) : "r"(addr));
}
__device__ __forceinline__ void mma16n8k16(float* d, const uint32_t* a,
                                           uint32_t b0, uint32_t b1) {
    asm volatile(
        "mma.sync.aligned.m16n8k16.row.col.f32.f16.f16.f32 "
        "{%0,%1,%2,%3}, {%4,%5,%6,%7}, {%8,%9}, {%0,%1,%2,%3};"
        : "+f"(d[0]), "+f"(d[1]), "+f"(d[2]), "+f"(d[3])
        : "r"(a[0]), "r"(a[1]), "r"(a[2]), "r"(a[3]), "r"(b0), "r"(b1));
}
__device__ __forceinline__ uint32_t pack_h2(float lo, float hi) {
    uint32_t r;
    asm("cvt.rn.f16x2.f32 %0, %1, %2;" : "=r"(r) : "f"(hi), "f"(lo));
    return r;
}

// ---------------- per-head parameters --------------------------------------
__global__ void hparams_kernel(const float* __restrict__ A_log,
                               const float* __restrict__ dt_bias) {
    int h = threadIdx.x;
    if (h < NH) {
        float xv = 0.1f + dt_bias[h];
        float sp = (xv > 20.f) ? xv : log1pf(expf(xv));
        g_dt[h] = sp;
        g_a[h]  = -expf(A_log[h]) * sp;
    }
}

// ---------------- fp32 -> fp16 conversion ----------------------------------
__global__ void to_half_kernel(const float* __restrict__ in, __half* __restrict__ out, int n8) {
    int i = blockIdx.x * blockDim.x + threadIdx.x;
    int stride = gridDim.x * blockDim.x;
    for (; i < n8; i += stride) {
        float4 a = ((const float4*)in)[2 * i];
        float4 b = ((const float4*)in)[2 * i + 1];
        uint4 o;
        o.x = pack_h2(a.x, a.y);
        o.y = pack_h2(a.z, a.w);
        o.z = pack_h2(b.x, b.y);
        o.w = pack_h2(b.z, b.w);
        ((uint4*)out)[i] = o;
    }
}

// ---------------- mma.sync FP16 GEMM: C[M,N] = A[M,K]*B[N,K]^T -------------
#define KTH      64
#define ALDH     72
#define A_H      (128 * ALDH)
#define B_H      (256 * ALDH)
#define STGB     ((A_H + B_H) * 2)           // 55296 B
#define NSTG     4
#define GM_SMEM  (NSTG * STGB)               // 221184 B

__global__ __launch_bounds__(512, 1)
void gemm_mma(const __half* __restrict__ A, const __half* __restrict__ B,
              float* __restrict__ C, int M, int N, int K, int tiles_m) {
    extern __shared__ __align__(16) char smraw[];
    uint32_t sbase = s2u(smraw);

    int tid = threadIdx.x, lane = tid & 31, wid = tid >> 5;
    int wm = (wid & 1) * 64;
    int wn = (wid >> 1) * 32;
    int bid = blockIdx.x;
    int m0 = (bid % tiles_m) * 128;
    int n0 = (bid / tiles_m) * 256;

    const __half* gA[2]; uint32_t oA[2];
    #pragma unroll
    for (int it = 0; it < 2; it++) {
        int q = tid + it * 512;
        int r = q >> 3, c8 = (q & 7) * 8;
        gA[it] = A + (size_t)(m0 + r) * K + c8;
        oA[it] = (uint32_t)(r * ALDH + c8) * 2;
    }
    const __half* gB[4]; uint32_t oB[4];
    #pragma unroll
    for (int it = 0; it < 4; it++) {
        int q = tid + it * 512;
        int r = q >> 3, c8 = (q & 7) * 8;
        gB[it] = B + (size_t)(n0 + r) * K + c8;
        oB[it] = (uint32_t)(A_H + r * ALDH + c8) * 2;
    }

    int lr = lane & 7;
    int a_row = lr + ((lane >> 3) & 1) * 8;
    int a_col = ((lane >> 4) & 1) * 8;
    uint32_t aoff[4];
    #pragma unroll
    for (int t = 0; t < 4; t++)
        aoff[t] = sbase + (uint32_t)(((wm + t * 16 + a_row) * ALDH + a_col) * 2);
    int b_row = lr + ((lane >> 4) & 1) * 8;
    int b_col = ((lane >> 3) & 1) * 8;
    uint32_t boff[2];
    #pragma unroll
    for (int v = 0; v < 2; v++)
        boff[v] = sbase + (uint32_t)((A_H + (wn + v * 16 + b_row) * ALDH + b_col) * 2);

    const int NKC = K / KTH;

    #pragma unroll
    for (int s = 0; s < NSTG - 1; s++) {
        uint32_t sb = sbase + s * STGB;
        #pragma unroll
        for (int it = 0; it < 2; it++) cpasync16(sb + oA[it], gA[it] + s * KTH);
        #pragma unroll
        for (int it = 0; it < 4; it++) cpasync16(sb + oB[it], gB[it] + s * KTH);
        asm volatile("cp.async.commit_group;");
    }

    float acc[4][4][4];
    #pragma unroll
    for (int t = 0; t < 4; t++)
        #pragma unroll
        for (int u = 0; u < 4; u++)
            #pragma unroll
            for (int v = 0; v < 4; v++) acc[t][u][v] = 0.f;

    for (int kb = 0; kb < NKC; kb++) {
        int st = kb & (NSTG - 1);
        asm volatile("cp.async.wait_group %0;" :: "n"(NSTG - 2));
        __syncthreads();

        {
            int fc = kb + NSTG - 1;
            if (fc < NKC) {
                uint32_t sb = sbase + (fc & (NSTG - 1)) * STGB;
                #pragma unroll
                for (int it = 0; it < 2; it++) cpasync16(sb + oA[it], gA[it] + fc * KTH);
                #pragma unroll
                for (int it = 0; it < 4; it++) cpasync16(sb + oB[it], gB[it] + fc * KTH);
            }
            asm volatile("cp.async.commit_group;");
        }

        uint32_t stb = st * STGB;
        #pragma unroll
        for (int ks = 0; ks < 4; ks++) {
            uint32_t kadd = stb + ks * 32;
            uint32_t af[4][4];
            #pragma unroll
            for (int t = 0; t < 4; t++) ldsm4(af[t], aoff[t] + kadd);
            uint32_t bf[2][4];
            #pragma unroll
            for (int v = 0; v < 2; v++) ldsm4(bf[v], boff[v] + kadd);
            #pragma unroll
            for (int u = 0; u < 4; u++) {
                uint32_t b0 = bf[u >> 1][(u & 1) * 2 + 0];
                uint32_t b1 = bf[u >> 1][(u & 1) * 2 + 1];
                #pragma unroll
                for (int t = 0; t < 4; t++) mma16n8k16(acc[t][u], af[t], b0, b1);
            }
        }
    }

    int g4 = lane >> 2, c4i = lane & 3;
    #pragma unroll
    for (int t = 0; t < 4; t++) {
        int r0 = m0 + wm + t * 16 + g4;
        #pragma unroll
        for (int u = 0; u < 4; u++) {
            int col = n0 + wn + u * 8 + c4i * 2;
            *(float2*)&C[(size_t)r0 * N + col] = make_float2(acc[t][u][0], acc[t][u][1]);
            *(float2*)&C[(size_t)(r0 + 8) * N + col] = make_float2(acc[t][u][2], acc[t][u][3]);
        }
    }
}

// ---------------- G = C @ B^T per (chunk, group) ----------------------------
// 128x128x64 fp16 mma; output fp16 to g_G[k][g][i][j].
#define GALD 72
__global__ __launch_bounds__(256)
void gemmG_kernel() {
    __shared__ __align__(16) __half sC[128 * GALD];
    __shared__ __align__(16) __half sB[128 * GALD];
    int k = blockIdx.x, g = blockIdx.y;
    int tid = threadIdx.x, lane = tid & 31, wid = tid >> 5;
    int lb = k * CHUNKSZ;

    // load C/B chunk: 2 tiles x 128 rows x 8 uint4/row = 2048 uint4 total
    #pragma unroll
    for (int it = 0; it < 8; it++) {
        int q = tid + it * 256;
        int which = q >> 10, rem = q & 1023;
        int r = rem >> 3, c8 = (rem & 7) * 8;
        const __half* src = (which ? g_Bh : g_Ch) + ((size_t)(lb + r) * NG + g) * DS + c8;
        __half* dst = (which ? sB : sC) + r * GALD + c8;
        *(uint4*)dst = *(const uint4*)src;
    }
    __syncthreads();

    uint32_t sCb = s2u(sC), sBb = s2u(sB);
    int wm = (wid & 1) * 64, wn = (wid >> 1) * 32;
    int lr = lane & 7;
    int a_row = lr + ((lane >> 3) & 1) * 8;
    int a_col = ((lane >> 4) & 1) * 8;
    uint32_t aoff[4];
    #pragma unroll
    for (int t = 0; t < 4; t++)
        aoff[t] = sCb + (uint32_t)(((wm + t * 16 + a_row) * GALD + a_col) * 2);
    int b_row = lr + ((lane >> 4) & 1) * 8;
    int b_col = ((lane >> 3) & 1) * 8;
    uint32_t boff[2];
    #pragma unroll
    for (int v = 0; v < 2; v++)
        boff[v] = sBb + (uint32_t)(((wn + v * 16 + b_row) * GALD + b_col) * 2);

    float acc[4][4][4];
    #pragma unroll
    for (int t = 0; t < 4; t++)
        #pragma unroll
        for (int u = 0; u < 4; u++)
            #pragma unroll
            for (int v = 0; v < 4; v++) acc[t][u][v] = 0.f;

    #pragma unroll
    for (int ks = 0; ks < 4; ks++) {
        uint32_t kadd = ks * 32;
        uint32_t af[4][4];
        #pragma unroll
        for (int t = 0; t < 4; t++) ldsm4(af[t], aoff[t] + kadd);
        uint32_t bf[2][4];
        #pragma unroll
        for (int v = 0; v < 2; v++) ldsm4(bf[v], boff[v] + kadd);
        #pragma unroll
        for (int u = 0; u < 4; u++) {
            uint32_t b0 = bf[u >> 1][(u & 1) * 2 + 0];
            uint32_t b1 = bf[u >> 1][(u & 1) * 2 + 1];
            #pragma unroll
            for (int t = 0; t < 4; t++) mma16n8k16(acc[t][u], af[t], b0, b1);
        }
    }

    __half* Gout = g_G + ((size_t)(k * NG + g) << 14);
    int g4 = lane >> 2, c4i = lane & 3;
    #pragma unroll
    for (int t = 0; t < 4; t++) {
        int r0 = wm + t * 16 + g4;
        #pragma unroll
        for (int u = 0; u < 4; u++) {
            int col = wn + u * 8 + c4i * 2;
            *(uint32_t*)&Gout[r0 * 128 + col] = pack_h2(acc[t][u][0], acc[t][u][1]);
            *(uint32_t*)&Gout[(r0 + 8) * 128 + col] = pack_h2(acc[t][u][2], acc[t][u][3]);
        }
    }
}

// ---------------- per-chunk end states: S[k,h,p,n] --------------------------
__global__ void states_kernel(const float* __restrict__ Bin) {
    int k = blockIdx.x, h = blockIdx.y;
    int tid = threadIdx.x;
    int p = tid & 63, quad = tid >> 6;
    float a = g_a[h], dtv = g_dt[h];
    int g = h / HPG;
    __shared__ float sx[8 * 64], sbuf[8 * 64];
    float acc[16];
    #pragma unroll
    for (int m = 0; m < 16; m++) acc[m] = 0.f;
    int lb = k * CHUNKSZ;
    for (int jb = 0; jb < CHUNKSZ; jb += 8) {
        __syncthreads();
        #pragma unroll
        for (int it = 0; it < 2; it++) {
            int e = tid + it * 256;
            int jj = e >> 6, pp = e & 63;
            int l = lb + jb + jj;
            sx[e] = g_xz[(size_t)l * IN2 + h * HD + pp];
            sbuf[e] = Bin[((size_t)l * NG + g) * DS + pp];
        }
        __syncthreads();
        #pragma unroll
        for (int jj = 0; jj < 8; jj++) {
            int j = jb + jj;
            float dec = expf(a * (float)(CHUNKSZ - 1 - j)) * dtv;
            float v = sx[jj * 64 + p] * dec;
            #pragma unroll
            for (int m = 0; m < 16; m++)
                acc[m] += v * sbuf[jj * 64 + quad + 4 * m];
        }
    }
    size_t base = ((size_t)(k * NH + h)) << 12;
    #pragma unroll
    for (int m = 0; m < 16; m++)
        g_states[base + p * 64 + quad + 4 * m] = acc[m];
}

// ---------------- inter-chunk scan (fp16 prev out, [p][n]) ------------------
__global__ void scan_kernel() {
    int h = blockIdx.x;
    float cd = expf(g_a[h] * (float)CHUNKSZ);
    for (int e = threadIdx.x; e < HD * DS; e += 256) {
        float carry = 0.f;
        #pragma unroll
        for (int k = 0; k < NCHUNK; k++) {
            size_t base = ((size_t)(k * NH + h)) << 12;
            g_prevh[base + e] = __float2half(carry);
            carry = carry * cd + g_states[base + e];
        }
    }
}

// ---------------- yblock: Y = [G' | C*exp] @ [X^T | prev]^T via mma ---------
// Per (chunk k, head h). A[128][192] fp16, B[64][192] fp16, K=192.
#define KTOT 192
#define ALD2 200
#define YB_SMEM ((128 * ALD2 + 64 * ALD2) * 2 + 132 * 4)

__global__ __launch_bounds__(256, 2)
void yblock_mma(const float* __restrict__ Cin, const float* __restrict__ Dv) {
    extern __shared__ __align__(16) char sraw[];
    __half* sA  = (__half*)sraw;               // [128][ALD2]
    __half* sBt = sA + 128 * ALD2;             // [64][ALD2]
    float* sDec = (float*)(sBt + 64 * ALD2);   // [132]

    int k = blockIdx.x, h = blockIdx.y;
    int tid = threadIdx.x, lane = tid & 31, wid = tid >> 5;
    float a = g_a[h], dtv = g_dt[h], Dh = Dv[h];
    int g = h / HPG;
    int lb = k * CHUNKSZ;

    for (int d = tid; d < 130; d += 256) sDec[d] = expf(a * (float)d);
    __syncthreads();

    // A cols 0..127: masked & decayed G
    {
        const __half* Gh = g_G + ((size_t)(k * NG + g) << 14);
        for (int q = tid; q < 128 * 64; q += 256) {
            int i = q >> 6, j2 = (q & 63) * 2;
            __half2 gv = *(const __half2*)&Gh[i * 128 + j2];
            float2 f = __half22float2(gv);
            float w0 = (j2 <= i) ? f.x * dtv * sDec[i - j2] : 0.f;
            float w1 = (j2 + 1 <= i) ? f.y * dtv * sDec[i - j2 - 1] : 0.f;
            *(uint32_t*)&sA[i * ALD2 + j2] = pack_h2(w0, w1);
        }
    }
    // A cols 128..191: C * exp((i+1)a)
    for (int q = tid; q < 128 * 16; q += 256) {
        int i = q >> 4, n4 = (q & 15) * 4;
        float4 c = *(const float4*)&Cin[((size_t)(lb + i) * NG + g) * DS + n4];
        float sc = sDec[i + 1];
        uint2 o;
        o.x = pack_h2(c.x * sc, c.y * sc);
        o.y = pack_h2(c.z * sc, c.w * sc);
        *(uint2*)&sA[i * ALD2 + 128 + n4] = o;
    }
    // B cols 0..127: X^T (x[j,p] -> sBt[p][j]), fp32 -> fp16
    for (int q = tid; q < 64 * 16; q += 256) {
        int j = (q >> 4) * 2, p4 = (q & 15) * 4;
        const float* x0 = &g_xz[(size_t)(lb + j) * IN2 + h * HD + p4];
        const float* x1 = x0 + IN2;
        float4 v0 = *(const float4*)x0;
        float4 v1 = *(const float4*)x1;
        *(uint32_t*)&sBt[(p4 + 0) * ALD2 + j] = pack_h2(v0.x, v1.x);
        *(uint32_t*)&sBt[(p4 + 1) * ALD2 + j] = pack_h2(v0.y, v1.y);
        *(uint32_t*)&sBt[(p4 + 2) * ALD2 + j] = pack_h2(v0.z, v1.z);
        *(uint32_t*)&sBt[(p4 + 3) * ALD2 + j] = pack_h2(v0.w, v1.w);
    }
    // B cols 128..191: prev fp16 [p][n]
    {
        const uint4* Pv = (const uint4*)(g_prevh + ((size_t)(k * NH + h) << 12));
        for (int q = tid; q < 512; q += 256) {
            int p = q >> 3, c8 = (q & 7) * 8;
            *(uint4*)&sBt[p * ALD2 + 128 + c8] = Pv[q];
        }
    }
    __syncthreads();

    // mma: 8 warps 2m x 4n, warp tile 64x16
    uint32_t sAb = s2u(sA), sBb = s2u(sBt);
    int wm = (wid & 1) * 64, wn = (wid >> 1) * 16;
    int lr = lane & 7;
    int a_row = lr + ((lane >> 3) & 1) * 8;
    int a_col = ((lane >> 4) & 1) * 8;
    uint32_t aoff[4];
    #pragma unroll
    for (int t = 0; t < 4; t++)
        aoff[t] = sAb + (uint32_t)(((wm + t * 16 + a_row) * ALD2 + a_col) * 2);
    int b_row = lr + ((lane >> 4) & 1) * 8;
    int b_col = ((lane >> 3) & 1) * 8;
    uint32_t boff = sBb + (uint32_t)(((wn + b_row) * ALD2 + b_col) * 2);

    float acc[4][2][4];
    #pragma unroll
    for (int t = 0; t < 4; t++)
        #pragma unroll
        for (int u = 0; u < 2; u++)
            #pragma unroll
            for (int v = 0; v < 4; v++) acc[t][u][v] = 0.f;

    #pragma unroll
    for (int ks = 0; ks < KTOT / 16; ks++) {
        uint32_t kadd = ks * 32;
        uint32_t af[4][4];
        #pragma unroll
        for (int t = 0; t < 4; t++) ldsm4(af[t], aoff[t] + kadd);
        uint32_t bf[4];
        ldsm4(bf, boff + kadd);
        #pragma unroll
        for (int u = 0; u < 2; u++) {
            uint32_t b0 = bf[u * 2 + 0];
            uint32_t b1 = bf[u * 2 + 1];
            #pragma unroll
            for (int t = 0; t < 4; t++) mma16n8k16(acc[t][u], af[t], b0, b1);
        }
    }

    // epilogue: + x*D, sigmoid gate, fp16 store
    int g4 = lane >> 2, c4i = lane & 3;
    #pragma unroll
    for (int t = 0; t < 4; t++) {
        #pragma unroll
        for (int half_ = 0; half_ < 2; half_++) {
            int i = wm + t * 16 + g4 + half_ * 8;
            int l = lb + i;
            #pragma unroll
            for (int u = 0; u < 2; u++) {
                int p = wn + u * 8 + c4i * 2;
                float y0 = acc[t][u][half_ * 2 + 0];
                float y1 = acc[t][u][half_ * 2 + 1];
                float x0 = __half2float(sBt[p * ALD2 + i]);
                float x1 = __half2float(sBt[(p + 1) * ALD2 + i]);
                float2 zv = *(const float2*)&g_xz[(size_t)l * IN2 + INNER + h * HD + p];
                y0 = (y0 + x0 * Dh) / (1.f + expf(-zv.x));
                y1 = (y1 + x1 * Dh) / (1.f + expf(-zv.y));
                *(uint32_t*)&g_ygh[(size_t)l * INNER + h * HD + p] = pack_h2(y0, y1);
            }
        }
    }
}

// ---------------- launcher --------------------------------------------------
extern "C" void kernel_launch(void* const* d_in, const int* in_sizes, int n_in,
                              void* d_out, int out_size) {
    (void)in_sizes; (void)n_in; (void)out_size;
    const float* hidden = (const float*)d_in[0];
    const float* W_in   = (const float*)d_in[1];
    const float* W_out  = (const float*)d_in[2];
    const float* A_log  = (const float*)d_in[3];
    const float* Dv     = (const float*)d_in[4];
    const float* dtb    = (const float*)d_in[5];
    const float* Bin    = (const float*)d_in[6];
    const float* Cin    = (const float*)d_in[7];
    float* out = (float*)d_out;

    float *xz_ptr;
    __half *ygh_ptr, *hidh_ptr, *w1h_ptr, *w2h_ptr, *bh_ptr, *ch_ptr;
    cudaGetSymbolAddress((void**)&xz_ptr, g_xz);
    cudaGetSymbolAddress((void**)&ygh_ptr, g_ygh);
    cudaGetSymbolAddress((void**)&hidh_ptr, g_hidh);
    cudaGetSymbolAddress((void**)&w1h_ptr, g_w1h);
    cudaGetSymbolAddress((void**)&w2h_ptr, g_w2h);
    cudaGetSymbolAddress((void**)&bh_ptr, g_Bh);
    cudaGetSymbolAddress((void**)&ch_ptr, g_Ch);

    cudaFuncSetAttribute(gemm_mma, cudaFuncAttributeMaxDynamicSharedMemorySize, GM_SMEM);
    cudaFuncSetAttribute(yblock_mma, cudaFuncAttributeMaxDynamicSharedMemorySize, YB_SMEM);

    // launch order: gemm1 is 4th (ncu captures it)
    hparams_kernel<<<1, 128>>>(A_log, dtb);                                   // 1
    to_half_kernel<<<1184, 256>>>(W_in,   w1h_ptr,  (IN2 * DMODEL) / 8);      // 2
    to_half_kernel<<<1184, 256>>>(hidden, hidh_ptr, (L_TOK * DMODEL) / 8);    // 3

    // GEMM1: xz[L, IN2] = hid @ W_in^T
    {
        int tiles_m = L_TOK / 128;
        int tiles_n = IN2 / 256;
        gemm_mma<<<tiles_m * tiles_n, 512, GM_SMEM>>>(hidh_ptr, w1h_ptr, xz_ptr,
                                                      L_TOK, IN2, DMODEL, tiles_m);  // 4
    }

    to_half_kernel<<<256, 256>>>(Bin, bh_ptr, (L_TOK * NG * DS) / 8);         // 5
    to_half_kernel<<<256, 256>>>(Cin, ch_ptr, (L_TOK * NG * DS) / 8);         // 6
    gemmG_kernel<<<dim3(NCHUNK, NG), 256>>>();                                // 7
    states_kernel<<<dim3(NCHUNK, NH), 256>>>(Bin);                            // 8
    scan_kernel<<<NH, 256>>>();                                               // 9
    yblock_mma<<<dim3(NCHUNK, NH), 256, YB_SMEM>>>(Cin, Dv);                  // 10

    to_half_kernel<<<1184, 256>>>(W_out, w2h_ptr, (DMODEL * INNER) / 8);      // 11

    // GEMM2: out[L, DMODEL] = yg @ W_out^T
    {
        int tiles_m = L_TOK / 128;
        int tiles_n = DMODEL / 256;
        gemm_mma<<<tiles_m * tiles_n, 512, GM_SMEM>>>(ygh_ptr, w2h_ptr, out,
                                                      L_TOK, DMODEL, INNER, tiles_m); // 12
    }
}